// round 3
// baseline (speedup 1.0000x reference)
#include <cuda_runtime.h>
#include <cstdint>

#define NN 100000
#define EE 400000
#define BBATCH 2048
#define HID 128
#define LL 4
#define NEG_SLOPE 0.2f

// ------------------------- device scratch (static, no allocs) ----------------
__device__ __align__(128) float g_h[NN * HID];      // node features (updated per layer)
__device__ __align__(128) float g_xh[NN * HID];     // h @ gat_lin_w[l]
__device__ __align__(128) float g_out[NN * HID];    // aggregation accumulator
__device__ __align__(128) float g_as[NN * 4];
__device__ __align__(128) float g_ad[NN * 4];
__device__ __align__(128) float g_denom[NN * 4];
__device__ __align__(128) float g_ae[LL * EE * 4];  // [l][E][4] attention edge terms
__device__ __align__(128) float g_ael[LL * NN * 4]; // [l][N][4] self-loop edge terms
__device__ __align__(128) float g_deg[NN];
__device__ __align__(128) float g_M[LL * 4 * 4];    // [l][f(3=bias)][h]
__device__ __align__(128) float g_bnscale[LL * HID];
__device__ __align__(128) float g_cnt[BBATCH];
__device__ __align__(128) float g_gsum[BBATCH * HID];
__device__ __align__(128) unsigned g_gmax[BBATCH * HID];

// ------------------------- helpers ----------------
__device__ __forceinline__ unsigned enc_f(float f) {
    unsigned u = __float_as_uint(f);
    return (u & 0x80000000u) ? ~u : (u | 0x80000000u);
}
__device__ __forceinline__ float dec_f(unsigned e) {
    return (e & 0x80000000u) ? __uint_as_float(e & 0x7fffffffu) : __uint_as_float(~e);
}

// ------------------------- setup: w_e_att collapse + bn scale ----------------
__global__ void setup_kernel(const float* __restrict__ edge_w, const float* __restrict__ edge_b,
                             const float* __restrict__ gat_edge_w, const float* __restrict__ att_edge,
                             const float* __restrict__ bn_gamma, const float* __restrict__ bn_var) {
    __shared__ float S[LL * 128 * 4]; // [l][k][h]
    int t = threadIdx.x;
    for (int i = t; i < LL * 128 * 4; i += 256) {
        int l = i >> 9, k = (i >> 2) & 127, h = i & 3;
        const float* wrow = gat_edge_w + (l * 128 + k) * 128 + h * 32;
        const float* arow = att_edge + l * 128 + h * 32;
        float s = 0.f;
        #pragma unroll
        for (int c = 0; c < 32; c++) s += wrow[c] * arow[c];
        S[l * 512 + k * 4 + h] = s;
    }
    __syncthreads();
    if (t < 64) {
        int l = t >> 4, f = (t >> 2) & 3, h = t & 3;
        float m = 0.f;
        if (f < 3) { for (int k = 0; k < 128; k++) m += edge_w[f * 128 + k] * S[l * 512 + k * 4 + h]; }
        else       { for (int k = 0; k < 128; k++) m += edge_b[k] * S[l * 512 + k * 4 + h]; }
        g_M[t] = m;
    }
    for (int i = t; i < LL * HID; i += 256)
        g_bnscale[i] = bn_gamma[i] * rsqrtf(bn_var[i] + 1e-5f);
}

// ------------------------- node encoder ----------------
__global__ void node_enc(const float* __restrict__ x, const float* __restrict__ w,
                         const float* __restrict__ b, int n) {
    int i = blockIdx.x * blockDim.x + threadIdx.x;
    if (i >= n * HID) return;
    int node = i >> 7, j = i & 127;
    const float* xr = x + node * 7;
    float s = b[j];
    #pragma unroll
    for (int f = 0; f < 7; f++) s += xr[f] * w[f * HID + j];
    g_h[i] = s;
}

// ------------------------- zero kernels ----------------
__global__ void zero_pre(int n) {
    int tid = blockIdx.x * blockDim.x + threadIdx.x;
    int stride = gridDim.x * blockDim.x;
    for (int i = tid; i < n; i += stride) g_deg[i] = 0.f;
    for (int i = tid; i < LL * n * 4; i += stride) g_ael[i] = 0.f;
}
__global__ void zero_layer(int n) {
    int tid = blockIdx.x * blockDim.x + threadIdx.x;
    int stride = gridDim.x * blockDim.x;
    for (int i = tid; i < n * HID; i += stride) g_out[i] = 0.f;
    for (int i = tid; i < n * 4; i += stride) g_denom[i] = 0.f;
}
__global__ void zero_readout(int b) {
    int tid = blockIdx.x * blockDim.x + threadIdx.x;
    int stride = gridDim.x * blockDim.x;
    for (int i = tid; i < b; i += stride) g_cnt[i] = 0.f;
    for (int i = tid; i < b * HID; i += stride) { g_gsum[i] = 0.f; g_gmax[i] = 0x007fffffu; }
}

// ------------------------- edge attention precompute (all layers) ----------------
__global__ void edge_att_pre(const float* __restrict__ edge_attr, const int* __restrict__ ei,
                             int E, int n) {
    int j = blockIdx.x * blockDim.x + threadIdx.x;
    if (j >= E) return;
    float e0 = edge_attr[j * 3], e1 = edge_attr[j * 3 + 1], e2 = edge_attr[j * 3 + 2];
    int dst = ei[E + j];
    atomicAdd(&g_deg[dst], 1.0f);
    #pragma unroll
    for (int l = 0; l < LL; l++) {
        #pragma unroll
        for (int h = 0; h < 4; h++) {
            float a = e0 * g_M[l * 16 + h] + e1 * g_M[l * 16 + 4 + h] +
                      e2 * g_M[l * 16 + 8 + h] + g_M[l * 16 + 12 + h];
            g_ae[(l * E + j) * 4 + h] = a;
            atomicAdd(&g_ael[(l * n + dst) * 4 + h], a);
        }
    }
}
__global__ void loop_att_fin(int n) {
    int i = blockIdx.x * blockDim.x + threadIdx.x;
    if (i >= LL * n * 4) return;
    int node = (i >> 2) % n;
    g_ael[i] *= (1.0f / fmaxf(g_deg[node], 1.0f));
}

// ------------------------- GAT GEMM: xh = h @ W, + a_s / a_d epilogue -------
// block: 256 threads, computes 64 rows x 128 cols, packed f32x2 FMA.
__global__ __launch_bounds__(256) void gat_gemm(const float* __restrict__ W,
                                                const float* __restrict__ atts,
                                                const float* __restrict__ attd, int n) {
    __shared__ __align__(16) float As2[64 * 32 * 2]; // [row][kk] duplicated pairs
    __shared__ __align__(16) float Bs[32 * 128];
    int t = threadIdx.x;
    int tc = t & 31, tr = t >> 5;
    int n0 = blockIdx.x * 64;
    unsigned long long acc01[8], acc23[8];
    #pragma unroll
    for (int r = 0; r < 8; r++) { acc01[r] = 0ull; acc23[r] = 0ull; }

    for (int k0 = 0; k0 < 128; k0 += 32) {
        for (int q = t; q < 512; q += 256) {
            int row = q >> 3, kc = q & 7;
            int gr = n0 + row;
            float4 v = make_float4(0.f, 0.f, 0.f, 0.f);
            if (gr < n) v = *(const float4*)(g_h + gr * 128 + k0 + kc * 4);
            float2* dp = (float2*)As2 + row * 32 + kc * 4;
            dp[0] = make_float2(v.x, v.x); dp[1] = make_float2(v.y, v.y);
            dp[2] = make_float2(v.z, v.z); dp[3] = make_float2(v.w, v.w);
        }
        for (int q = t; q < 1024; q += 256) {
            int kk = q >> 5, j4 = q & 31;
            ((float4*)Bs)[kk * 32 + j4] = ((const float4*)(W + (k0 + kk) * 128))[j4];
        }
        __syncthreads();
        const unsigned long long* A8 = (const unsigned long long*)As2;
        #pragma unroll
        for (int kk = 0; kk < 32; kk++) {
            float4 bv = ((const float4*)Bs)[kk * 32 + tc];
            unsigned long long b01, b23;
            asm("mov.b64 %0, {%1,%2};" : "=l"(b01) : "f"(bv.x), "f"(bv.y));
            asm("mov.b64 %0, {%1,%2};" : "=l"(b23) : "f"(bv.z), "f"(bv.w));
            #pragma unroll
            for (int r = 0; r < 8; r++) {
                unsigned long long a2 = A8[(tr * 8 + r) * 32 + kk];
                asm("fma.rn.f32x2 %0, %1, %2, %0;" : "+l"(acc01[r]) : "l"(a2), "l"(b01));
                asm("fma.rn.f32x2 %0, %1, %2, %0;" : "+l"(acc23[r]) : "l"(a2), "l"(b23));
            }
        }
        __syncthreads();
    }

    int hd = tc >> 3;
    float4 avs = *(const float4*)(atts + hd * 32 + (tc & 7) * 4);
    float4 avd = *(const float4*)(attd + hd * 32 + (tc & 7) * 4);
    #pragma unroll
    for (int r = 0; r < 8; r++) {
        int row = n0 + tr * 8 + r;
        float2 v01 = *(float2*)&acc01[r];
        float2 v23 = *(float2*)&acc23[r];
        float4 vv = make_float4(v01.x, v01.y, v23.x, v23.y);
        if (row < n) *(float4*)(g_xh + row * 128 + tc * 4) = vv;
        float ps = vv.x * avs.x + vv.y * avs.y + vv.z * avs.z + vv.w * avs.w;
        float pd = vv.x * avd.x + vv.y * avd.y + vv.z * avd.z + vv.w * avd.w;
        #pragma unroll
        for (int off = 4; off; off >>= 1) {
            ps += __shfl_down_sync(0xffffffffu, ps, off, 8);
            pd += __shfl_down_sync(0xffffffffu, pd, off, 8);
        }
        if ((tc & 7) == 0 && row < n) {
            g_as[row * 4 + hd] = ps;
            g_ad[row * 4 + hd] = pd;
        }
    }
}

// ------------------------- edge pass: softmax-num aggregation ----------------
__global__ __launch_bounds__(256) void gat_edge(const int* __restrict__ ei, int E, int n, int l) {
    int widx = (blockIdx.x * blockDim.x + threadIdx.x) >> 5;
    int lane = threadIdx.x & 31;
    if (widx >= E + n) return;
    int src, dst;
    const float* aep;
    if (widx < E) {
        src = ei[widx]; dst = ei[E + widx];
        aep = g_ae + (l * E + widx) * 4;
    } else {
        src = dst = widx - E;
        aep = g_ael + (l * n + src) * 4;
    }
    int hd = lane >> 3;
    float alpha = g_as[src * 4 + hd] + g_ad[dst * 4 + hd] + aep[hd];
    alpha = alpha > 0.f ? alpha : NEG_SLOPE * alpha;
    float ex = __expf(alpha);
    if ((lane & 7) == 0) atomicAdd(&g_denom[dst * 4 + hd], ex);
    float4 xv = *(const float4*)(g_xh + src * 128 + lane * 4);
    float* op = g_out + dst * 128 + lane * 4;
    asm volatile("red.global.add.v4.f32 [%0], {%1,%2,%3,%4};"
                 :: "l"(op), "f"(xv.x * ex), "f"(xv.y * ex), "f"(xv.z * ex), "f"(xv.w * ex)
                 : "memory");
}

// ------------------------- finalize: /denom, bias, BN, relu, residual -------
__global__ void gat_finalize(const float* __restrict__ gat_bias, const float* __restrict__ bn_beta,
                             const float* __restrict__ bn_mean, int n, int l) {
    int i = blockIdx.x * blockDim.x + threadIdx.x;
    if (i >= n * 32) return;
    int node = i >> 5, q = i & 31, j = q * 4, hd = q >> 3;
    float inv = 1.0f / g_denom[node * 4 + hd];
    float4 o = *(float4*)(g_out + node * 128 + j);
    float4 hres = *(float4*)(g_h + node * 128 + j);
    const float* bs = g_bnscale + l * 128 + j;
    float4 r;
    r.x = fmaxf((o.x * inv + gat_bias[j + 0] - bn_mean[j + 0]) * bs[0] + bn_beta[j + 0], 0.f) + hres.x;
    r.y = fmaxf((o.y * inv + gat_bias[j + 1] - bn_mean[j + 1]) * bs[1] + bn_beta[j + 1], 0.f) + hres.y;
    r.z = fmaxf((o.z * inv + gat_bias[j + 2] - bn_mean[j + 2]) * bs[2] + bn_beta[j + 2], 0.f) + hres.z;
    r.w = fmaxf((o.w * inv + gat_bias[j + 3] - bn_mean[j + 3]) * bs[3] + bn_beta[j + 3], 0.f) + hres.w;
    *(float4*)(g_h + node * 128 + j) = r;
}

// ------------------------- readout: per-batch cnt/sum/max ----------------
__global__ __launch_bounds__(256) void readout(const int* __restrict__ batch, int n) {
    int widx = (blockIdx.x * blockDim.x + threadIdx.x) >> 5;
    int lane = threadIdx.x & 31;
    if (widx >= n) return;
    int b = batch[widx];
    if (lane == 0) atomicAdd(&g_cnt[b], 1.0f);
    float4 v = *(const float4*)(g_h + widx * 128 + lane * 4);
    float* sp = g_gsum + b * 128 + lane * 4;
    asm volatile("red.global.add.v4.f32 [%0], {%1,%2,%3,%4};"
                 :: "l"(sp), "f"(v.x), "f"(v.y), "f"(v.z), "f"(v.w) : "memory");
    unsigned* mp = g_gmax + b * 128 + lane * 4;
    atomicMax(mp + 0, enc_f(v.x));
    atomicMax(mp + 1, enc_f(v.y));
    atomicMax(mp + 2, enc_f(v.z));
    atomicMax(mp + 3, enc_f(v.w));
}

// ------------------------- fused head MLP (one block per graph) -------------
__global__ __launch_bounds__(128) void head(const float* __restrict__ gfeat,
        const float* __restrict__ gc_w, const float* __restrict__ gc_b,
        const float* __restrict__ gf1_w, const float* __restrict__ gf1_b,
        const float* __restrict__ gf2_w, const float* __restrict__ gf2_b,
        const float* __restrict__ p1_w, const float* __restrict__ p1_b,
        const float* __restrict__ p2_w, const float* __restrict__ p2_b,
        const float* __restrict__ p3_w, const float* __restrict__ p3_b,
        float* __restrict__ out) {
    int b = blockIdx.x, t = threadIdx.x;
    __shared__ float sG[384], sC[192], sT[64], sH1[128], sH2[64];
    float cnt = g_cnt[b];
    float inv = 1.0f / fmaxf(cnt, 1.0f);
    float gs = g_gsum[b * 128 + t];
    sG[t] = gs * inv;
    float mx = dec_f(g_gmax[b * 128 + t]);
    sG[128 + t] = (cnt > 0.f) ? mx : 0.f;
    sG[256 + t] = gs;
    if (t < 64) {
        float s = gf1_b[t];
        #pragma unroll
        for (int k = 0; k < 10; k++) s += gfeat[b * 10 + k] * gf1_w[k * 64 + t];
        sT[t] = fmaxf(s, 0.f);
    }
    __syncthreads();
    {
        float s = gc_b[t];
        #pragma unroll 8
        for (int k = 0; k < 384; k++) s += sG[k] * gc_w[k * 128 + t];
        sC[t] = fmaxf(s, 0.f);
    }
    if (t < 64) {
        float s = gf2_b[t];
        #pragma unroll 8
        for (int k = 0; k < 64; k++) s += sT[k] * gf2_w[k * 64 + t];
        sC[128 + t] = s;
    }
    __syncthreads();
    {
        float s = p1_b[t];
        #pragma unroll 8
        for (int k = 0; k < 192; k++) s += sC[k] * p1_w[k * 128 + t];
        sH1[t] = fmaxf(s, 0.f);
    }
    __syncthreads();
    if (t < 64) {
        float s = p2_b[t];
        #pragma unroll 8
        for (int k = 0; k < 128; k++) s += sH1[k] * p2_w[k * 64 + t];
        sH2[t] = fmaxf(s, 0.f);
    }
    __syncthreads();
    if (t < 5) {
        float s = p3_b[t];
        #pragma unroll
        for (int k = 0; k < 64; k++) s += sH2[k] * p3_w[k * 5 + t];
        out[b * 5 + t] = s;
    }
}

// ------------------------- launch ----------------
extern "C" void kernel_launch(void* const* d_in, const int* in_sizes, int n_in,
                              void* d_out, int out_size) {
    const float* x          = (const float*)d_in[0];
    const int*   ei         = (const int*)d_in[1];
    const float* edge_attr  = (const float*)d_in[2];
    const int*   batch      = (const int*)d_in[3];
    const float* gfeat      = (const float*)d_in[4];
    const float* node_w     = (const float*)d_in[5];
    const float* node_b     = (const float*)d_in[6];
    const float* edge_w     = (const float*)d_in[7];
    const float* edge_b     = (const float*)d_in[8];
    const float* gat_lin_w  = (const float*)d_in[9];
    const float* gat_edge_w = (const float*)d_in[10];
    const float* att_src    = (const float*)d_in[11];
    const float* att_dst    = (const float*)d_in[12];
    const float* att_edge   = (const float*)d_in[13];
    const float* gat_bias   = (const float*)d_in[14];
    const float* bn_gamma   = (const float*)d_in[15];
    const float* bn_beta    = (const float*)d_in[16];
    const float* bn_mean    = (const float*)d_in[17];
    const float* bn_var     = (const float*)d_in[18];
    const float* gc_w       = (const float*)d_in[19];
    const float* gc_b       = (const float*)d_in[20];
    const float* gf1_w      = (const float*)d_in[21];
    const float* gf1_b      = (const float*)d_in[22];
    const float* gf2_w      = (const float*)d_in[23];
    const float* gf2_b      = (const float*)d_in[24];
    const float* p1_w       = (const float*)d_in[25];
    const float* p1_b       = (const float*)d_in[26];
    const float* p2_w       = (const float*)d_in[27];
    const float* p2_b       = (const float*)d_in[28];
    const float* p3_w       = (const float*)d_in[29];
    const float* p3_b       = (const float*)d_in[30];

    int N = in_sizes[0] / 7;
    int E = in_sizes[1] / 2;
    int B = in_sizes[4] / 10;
    // defensive clamps: static scratch is sized for the dataset shapes
    if (N > NN) N = NN;
    if (E > EE) E = EE;
    if (B > BBATCH) B = BBATCH;

    setup_kernel<<<1, 256>>>(edge_w, edge_b, gat_edge_w, att_edge, bn_gamma, bn_var);
    node_enc<<<(N * HID + 255) / 256, 256>>>(x, node_w, node_b, N);
    zero_pre<<<1024, 256>>>(N);
    edge_att_pre<<<(E + 255) / 256, 256>>>(edge_attr, ei, E, N);
    loop_att_fin<<<(LL * N * 4 + 255) / 256, 256>>>(N);

    for (int l = 0; l < LL; l++) {
        zero_layer<<<2048, 256>>>(N);
        gat_gemm<<<(N + 63) / 64, 256>>>(gat_lin_w + (size_t)l * 128 * 128,
                                         att_src + l * 128, att_dst + l * 128, N);
        gat_edge<<<(E + N + 7) / 8, 256>>>(ei, E, N, l);
        gat_finalize<<<(N * 32 + 255) / 256, 256>>>(gat_bias + l * 128, bn_beta + l * 128,
                                                    bn_mean + l * 128, N, l);
    }

    zero_readout<<<1024, 256>>>(B);
    readout<<<(N + 7) / 8, 256>>>(batch, N);
    head<<<B, 128>>>(gfeat, gc_w, gc_b, gf1_w, gf1_b, gf2_w, gf2_b,
                     p1_w, p1_b, p2_w, p2_b, p3_w, p3_b, (float*)d_out);
}

// round 4
// speedup vs baseline: 1.0286x; 1.0286x over previous
#include <cuda_runtime.h>
#include <cstdint>

#define NN 100000
#define EE 400000
#define BBATCH 2048
#define HID 128
#define LL 4
#define NEG_SLOPE 0.2f

// ------------------------- device scratch (static, no allocs) ----------------
__device__ __align__(128) float g_h[NN * HID];      // node features (updated per layer)
__device__ __align__(128) float g_xh[NN * HID];     // h @ gat_lin_w[l]
__device__ __align__(128) float g_as[NN * 4];
__device__ __align__(128) float g_ad[NN * 4];
__device__ __align__(128) float g_M[LL * 4 * 4];    // [l][f(3=bias)][h]
__device__ __align__(128) float g_bnscale[LL * HID];
__device__ __align__(128) float g_cnt[BBATCH];
__device__ __align__(128) float g_gsum[BBATCH * HID];
__device__ __align__(128) unsigned g_gmax[BBATCH * HID];
// CSR by destination
__device__ __align__(128) int    g_degi[NN];
__device__ __align__(128) int    g_rowptr[NN + 1];
__device__ __align__(128) int    g_cursor[NN];
__device__ __align__(128) float4 g_csr[EE];         // {src(bits), e0, e1, e2}

// ------------------------- helpers ----------------
__device__ __forceinline__ unsigned enc_f(float f) {
    unsigned u = __float_as_uint(f);
    return (u & 0x80000000u) ? ~u : (u | 0x80000000u);
}
__device__ __forceinline__ float dec_f(unsigned e) {
    return (e & 0x80000000u) ? __uint_as_float(e & 0x7fffffffu) : __uint_as_float(~e);
}

// ------------------------- setup: w_e_att collapse + bn scale ----------------
__global__ void setup_kernel(const float* __restrict__ edge_w, const float* __restrict__ edge_b,
                             const float* __restrict__ gat_edge_w, const float* __restrict__ att_edge,
                             const float* __restrict__ bn_gamma, const float* __restrict__ bn_var) {
    __shared__ float S[LL * 128 * 4]; // [l][k][h]
    int t = threadIdx.x;
    for (int i = t; i < LL * 128 * 4; i += 256) {
        int l = i >> 9, k = (i >> 2) & 127, h = i & 3;
        const float* wrow = gat_edge_w + (l * 128 + k) * 128 + h * 32;
        const float* arow = att_edge + l * 128 + h * 32;
        float s = 0.f;
        #pragma unroll
        for (int c = 0; c < 32; c++) s += wrow[c] * arow[c];
        S[l * 512 + k * 4 + h] = s;
    }
    __syncthreads();
    if (t < 64) {
        int l = t >> 4, f = (t >> 2) & 3, h = t & 3;
        float m = 0.f;
        if (f < 3) { for (int k = 0; k < 128; k++) m += edge_w[f * 128 + k] * S[l * 512 + k * 4 + h]; }
        else       { for (int k = 0; k < 128; k++) m += edge_b[k] * S[l * 512 + k * 4 + h]; }
        g_M[t] = m;
    }
    for (int i = t; i < LL * HID; i += 256)
        g_bnscale[i] = bn_gamma[i] * rsqrtf(bn_var[i] + 1e-5f);
}

// ------------------------- node encoder ----------------
__global__ void node_enc(const float* __restrict__ x, const float* __restrict__ w,
                         const float* __restrict__ b, int n) {
    int i = blockIdx.x * blockDim.x + threadIdx.x;
    if (i >= n * HID) return;
    int node = i >> 7, j = i & 127;
    const float* xr = x + node * 7;
    float s = b[j];
    #pragma unroll
    for (int f = 0; f < 7; f++) s += xr[f] * w[f * HID + j];
    g_h[i] = s;
}

// ------------------------- CSR build ----------------
__global__ void zero_degi(int n) {
    int tid = blockIdx.x * blockDim.x + threadIdx.x;
    int stride = gridDim.x * blockDim.x;
    for (int i = tid; i < n; i += stride) g_degi[i] = 0;
}
__global__ void csr_count(const int* __restrict__ ei, int E) {
    int e = blockIdx.x * blockDim.x + threadIdx.x;
    if (e >= E) return;
    atomicAdd(&g_degi[ei[E + e]], 1);
}
__global__ __launch_bounds__(1024) void csr_scan(int n) {
    __shared__ int ssum[1024];
    int t = threadIdx.x;
    int chunk = (n + 1023) >> 10;
    int beg = t * chunk, end = beg + chunk;
    if (end > n) end = n;
    int s = 0;
    for (int i = beg; i < end; i++) s += g_degi[i];
    ssum[t] = s;
    __syncthreads();
    for (int off = 1; off < 1024; off <<= 1) {
        int v = (t >= off) ? ssum[t - off] : 0;
        __syncthreads();
        ssum[t] += v;
        __syncthreads();
    }
    int running = ssum[t] - s;   // exclusive prefix at chunk start
    for (int i = beg; i < end; i++) {
        g_rowptr[i] = running;
        g_cursor[i] = running;
        running += g_degi[i];
    }
    if (t == 1023) g_rowptr[n] = ssum[1023];
}
__global__ void csr_fill(const int* __restrict__ ei, const float* __restrict__ edge_attr, int E) {
    int e = blockIdx.x * blockDim.x + threadIdx.x;
    if (e >= E) return;
    int src = ei[e], dst = ei[E + e];
    int pos = atomicAdd(&g_cursor[dst], 1);
    g_csr[pos] = make_float4(__int_as_float(src),
                             edge_attr[e * 3], edge_attr[e * 3 + 1], edge_attr[e * 3 + 2]);
}

// ------------------------- GAT GEMM: xh = h @ W, + a_s / a_d epilogue -------
__global__ __launch_bounds__(256) void gat_gemm(const float* __restrict__ W,
                                                const float* __restrict__ atts,
                                                const float* __restrict__ attd, int n) {
    __shared__ __align__(16) float As2[64 * 32 * 2]; // [row][kk] duplicated pairs
    __shared__ __align__(16) float Bs[32 * 128];
    int t = threadIdx.x;
    int tc = t & 31, tr = t >> 5;
    int n0 = blockIdx.x * 64;
    unsigned long long acc01[8], acc23[8];
    #pragma unroll
    for (int r = 0; r < 8; r++) { acc01[r] = 0ull; acc23[r] = 0ull; }

    for (int k0 = 0; k0 < 128; k0 += 32) {
        for (int q = t; q < 512; q += 256) {
            int row = q >> 3, kc = q & 7;
            int gr = n0 + row;
            float4 v = make_float4(0.f, 0.f, 0.f, 0.f);
            if (gr < n) v = *(const float4*)(g_h + gr * 128 + k0 + kc * 4);
            float2* dp = (float2*)As2 + row * 32 + kc * 4;
            dp[0] = make_float2(v.x, v.x); dp[1] = make_float2(v.y, v.y);
            dp[2] = make_float2(v.z, v.z); dp[3] = make_float2(v.w, v.w);
        }
        for (int q = t; q < 1024; q += 256) {
            int kk = q >> 5, j4 = q & 31;
            ((float4*)Bs)[kk * 32 + j4] = ((const float4*)(W + (k0 + kk) * 128))[j4];
        }
        __syncthreads();
        const unsigned long long* A8 = (const unsigned long long*)As2;
        #pragma unroll
        for (int kk = 0; kk < 32; kk++) {
            float4 bv = ((const float4*)Bs)[kk * 32 + tc];
            unsigned long long b01, b23;
            asm("mov.b64 %0, {%1,%2};" : "=l"(b01) : "f"(bv.x), "f"(bv.y));
            asm("mov.b64 %0, {%1,%2};" : "=l"(b23) : "f"(bv.z), "f"(bv.w));
            #pragma unroll
            for (int r = 0; r < 8; r++) {
                unsigned long long a2 = A8[(tr * 8 + r) * 32 + kk];
                asm("fma.rn.f32x2 %0, %1, %2, %0;" : "+l"(acc01[r]) : "l"(a2), "l"(b01));
                asm("fma.rn.f32x2 %0, %1, %2, %0;" : "+l"(acc23[r]) : "l"(a2), "l"(b23));
            }
        }
        __syncthreads();
    }

    int hd = tc >> 3;
    float4 avs = *(const float4*)(atts + hd * 32 + (tc & 7) * 4);
    float4 avd = *(const float4*)(attd + hd * 32 + (tc & 7) * 4);
    #pragma unroll
    for (int r = 0; r < 8; r++) {
        int row = n0 + tr * 8 + r;
        float2 v01 = *(float2*)&acc01[r];
        float2 v23 = *(float2*)&acc23[r];
        float4 vv = make_float4(v01.x, v01.y, v23.x, v23.y);
        if (row < n) *(float4*)(g_xh + row * 128 + tc * 4) = vv;
        float ps = vv.x * avs.x + vv.y * avs.y + vv.z * avs.z + vv.w * avs.w;
        float pd = vv.x * avd.x + vv.y * avd.y + vv.z * avd.z + vv.w * avd.w;
        #pragma unroll
        for (int off = 4; off; off >>= 1) {
            ps += __shfl_down_sync(0xffffffffu, ps, off, 8);
            pd += __shfl_down_sync(0xffffffffu, pd, off, 8);
        }
        if ((tc & 7) == 0 && row < n) {
            g_as[row * 4 + hd] = ps;
            g_ad[row * 4 + hd] = pd;
        }
    }
}

// --------- fused per-dst aggregation: softmax + bias + BN + relu + residual --
// one warp per destination node; walks CSR, computes a_e inline, expf in 4 lanes.
__global__ __launch_bounds__(256) void gat_aggr(const float* __restrict__ gat_bias,
                                                const float* __restrict__ bn_beta,
                                                const float* __restrict__ bn_mean,
                                                int n, int l) {
    int w = (blockIdx.x * blockDim.x + threadIdx.x) >> 5;
    if (w >= n) return;
    int lane = threadIdx.x & 31;
    int hd = lane >> 3;
    bool alead = (lane & 7) == 0;

    float m0 = 0.f, m1 = 0.f, m2 = 0.f, m3 = 0.f, ad = 0.f;
    if (alead) {
        m0 = g_M[l * 16 + hd];      m1 = g_M[l * 16 + 4 + hd];
        m2 = g_M[l * 16 + 8 + hd];  m3 = g_M[l * 16 + 12 + hd];
        ad = g_ad[w * 4 + hd];
    }
    int s = g_rowptr[w], e = g_rowptr[w + 1];

    float4 acc = make_float4(0.f, 0.f, 0.f, 0.f);
    float denom = 0.f;
    float s0 = 0.f, s1 = 0.f, s2 = 0.f;

    for (int i = s; i < e; i++) {
        float4 ent = g_csr[i];                      // broadcast load
        int src = __float_as_int(ent.x);
        float ex = 0.f;
        if (alead) {
            float ae = ent.y * m0 + ent.z * m1 + ent.w * m2 + m3;
            float alpha = g_as[src * 4 + hd] + ad + ae;
            alpha = alpha > 0.f ? alpha : NEG_SLOPE * alpha;
            ex = __expf(alpha);
            denom += ex;
        }
        ex = __shfl_sync(0xffffffffu, ex, lane & 24);
        float4 xv = *(const float4*)(g_xh + (size_t)src * 128 + lane * 4);
        acc.x += ex * xv.x; acc.y += ex * xv.y; acc.z += ex * xv.z; acc.w += ex * xv.w;
        s0 += ent.y; s1 += ent.z; s2 += ent.w;
    }

    // self loop with mean incoming edge feature (0 if isolated)
    {
        float ex = 0.f;
        if (alead) {
            float invd = 1.f / fmaxf((float)(e - s), 1.f);
            float ae = (s0 * m0 + s1 * m1 + s2 * m2) * invd + m3;
            float alpha = g_as[w * 4 + hd] + ad + ae;
            alpha = alpha > 0.f ? alpha : NEG_SLOPE * alpha;
            ex = __expf(alpha);
            denom += ex;
        }
        ex = __shfl_sync(0xffffffffu, ex, lane & 24);
        float4 xv = *(const float4*)(g_xh + (size_t)w * 128 + lane * 4);
        acc.x += ex * xv.x; acc.y += ex * xv.y; acc.z += ex * xv.z; acc.w += ex * xv.w;
    }

    float inv = 0.f;
    if (alead) inv = 1.f / denom;
    inv = __shfl_sync(0xffffffffu, inv, lane & 24);

    int j = lane * 4;
    float4 hres = *(const float4*)(g_h + (size_t)w * 128 + j);
    const float* bs = g_bnscale + l * 128 + j;
    const float* gb = gat_bias + j;
    const float* bm = bn_mean + j;
    const float* bb = bn_beta + j;
    float4 r;
    r.x = fmaxf((acc.x * inv + gb[0] - bm[0]) * bs[0] + bb[0], 0.f) + hres.x;
    r.y = fmaxf((acc.y * inv + gb[1] - bm[1]) * bs[1] + bb[1], 0.f) + hres.y;
    r.z = fmaxf((acc.z * inv + gb[2] - bm[2]) * bs[2] + bb[2], 0.f) + hres.z;
    r.w = fmaxf((acc.w * inv + gb[3] - bm[3]) * bs[3] + bb[3], 0.f) + hres.w;
    *(float4*)(g_h + (size_t)w * 128 + j) = r;
}

// ------------------------- readout: per-batch cnt/sum/max ----------------
__global__ void zero_readout(int b) {
    int tid = blockIdx.x * blockDim.x + threadIdx.x;
    int stride = gridDim.x * blockDim.x;
    for (int i = tid; i < b; i += stride) g_cnt[i] = 0.f;
    for (int i = tid; i < b * HID; i += stride) { g_gsum[i] = 0.f; g_gmax[i] = 0x007fffffu; }
}
__global__ __launch_bounds__(256) void readout(const int* __restrict__ batch, int n) {
    int widx = (blockIdx.x * blockDim.x + threadIdx.x) >> 5;
    int lane = threadIdx.x & 31;
    if (widx >= n) return;
    int b = batch[widx];
    if (lane == 0) atomicAdd(&g_cnt[b], 1.0f);
    float4 v = *(const float4*)(g_h + (size_t)widx * 128 + lane * 4);
    float* sp = g_gsum + b * 128 + lane * 4;
    asm volatile("red.global.add.v4.f32 [%0], {%1,%2,%3,%4};"
                 :: "l"(sp), "f"(v.x), "f"(v.y), "f"(v.z), "f"(v.w) : "memory");
    unsigned* mp = g_gmax + b * 128 + lane * 4;
    atomicMax(mp + 0, enc_f(v.x));
    atomicMax(mp + 1, enc_f(v.y));
    atomicMax(mp + 2, enc_f(v.z));
    atomicMax(mp + 3, enc_f(v.w));
}

// ------------------------- fused head MLP (one block per graph) -------------
__global__ __launch_bounds__(128) void head(const float* __restrict__ gfeat,
        const float* __restrict__ gc_w, const float* __restrict__ gc_b,
        const float* __restrict__ gf1_w, const float* __restrict__ gf1_b,
        const float* __restrict__ gf2_w, const float* __restrict__ gf2_b,
        const float* __restrict__ p1_w, const float* __restrict__ p1_b,
        const float* __restrict__ p2_w, const float* __restrict__ p2_b,
        const float* __restrict__ p3_w, const float* __restrict__ p3_b,
        float* __restrict__ out) {
    int b = blockIdx.x, t = threadIdx.x;
    __shared__ float sG[384], sC[192], sT[64], sH1[128], sH2[64];
    float cnt = g_cnt[b];
    float inv = 1.0f / fmaxf(cnt, 1.0f);
    float gs = g_gsum[b * 128 + t];
    sG[t] = gs * inv;
    float mx = dec_f(g_gmax[b * 128 + t]);
    sG[128 + t] = (cnt > 0.f) ? mx : 0.f;
    sG[256 + t] = gs;
    if (t < 64) {
        float s = gf1_b[t];
        #pragma unroll
        for (int k = 0; k < 10; k++) s += gfeat[b * 10 + k] * gf1_w[k * 64 + t];
        sT[t] = fmaxf(s, 0.f);
    }
    __syncthreads();
    {
        float s = gc_b[t];
        #pragma unroll 8
        for (int k = 0; k < 384; k++) s += sG[k] * gc_w[k * 128 + t];
        sC[t] = fmaxf(s, 0.f);
    }
    if (t < 64) {
        float s = gf2_b[t];
        #pragma unroll 8
        for (int k = 0; k < 64; k++) s += sT[k] * gf2_w[k * 64 + t];
        sC[128 + t] = s;
    }
    __syncthreads();
    {
        float s = p1_b[t];
        #pragma unroll 8
        for (int k = 0; k < 192; k++) s += sC[k] * p1_w[k * 128 + t];
        sH1[t] = fmaxf(s, 0.f);
    }
    __syncthreads();
    if (t < 64) {
        float s = p2_b[t];
        #pragma unroll 8
        for (int k = 0; k < 128; k++) s += sH1[k] * p2_w[k * 64 + t];
        sH2[t] = fmaxf(s, 0.f);
    }
    __syncthreads();
    if (t < 5) {
        float s = p3_b[t];
        #pragma unroll
        for (int k = 0; k < 64; k++) s += sH2[k] * p3_w[k * 5 + t];
        out[b * 5 + t] = s;
    }
}

// ------------------------- launch ----------------
extern "C" void kernel_launch(void* const* d_in, const int* in_sizes, int n_in,
                              void* d_out, int out_size) {
    const float* x          = (const float*)d_in[0];
    const int*   ei         = (const int*)d_in[1];
    const float* edge_attr  = (const float*)d_in[2];
    const int*   batch      = (const int*)d_in[3];
    const float* gfeat      = (const float*)d_in[4];
    const float* node_w     = (const float*)d_in[5];
    const float* node_b     = (const float*)d_in[6];
    const float* edge_w     = (const float*)d_in[7];
    const float* edge_b     = (const float*)d_in[8];
    const float* gat_lin_w  = (const float*)d_in[9];
    const float* gat_edge_w = (const float*)d_in[10];
    const float* att_src    = (const float*)d_in[11];
    const float* att_dst    = (const float*)d_in[12];
    const float* att_edge   = (const float*)d_in[13];
    const float* gat_bias   = (const float*)d_in[14];
    const float* bn_gamma   = (const float*)d_in[15];
    const float* bn_beta    = (const float*)d_in[16];
    const float* bn_mean    = (const float*)d_in[17];
    const float* bn_var     = (const float*)d_in[18];
    const float* gc_w       = (const float*)d_in[19];
    const float* gc_b       = (const float*)d_in[20];
    const float* gf1_w      = (const float*)d_in[21];
    const float* gf1_b      = (const float*)d_in[22];
    const float* gf2_w      = (const float*)d_in[23];
    const float* gf2_b      = (const float*)d_in[24];
    const float* p1_w       = (const float*)d_in[25];
    const float* p1_b       = (const float*)d_in[26];
    const float* p2_w       = (const float*)d_in[27];
    const float* p2_b       = (const float*)d_in[28];
    const float* p3_w       = (const float*)d_in[29];
    const float* p3_b       = (const float*)d_in[30];

    int N = in_sizes[0] / 7;
    int E = in_sizes[1] / 2;
    int B = in_sizes[4] / 10;
    if (N > NN) N = NN;
    if (E > EE) E = EE;
    if (B > BBATCH) B = BBATCH;

    setup_kernel<<<1, 256>>>(edge_w, edge_b, gat_edge_w, att_edge, bn_gamma, bn_var);
    node_enc<<<(N * HID + 255) / 256, 256>>>(x, node_w, node_b, N);

    // CSR build (once)
    zero_degi<<<256, 256>>>(N);
    csr_count<<<(E + 255) / 256, 256>>>(ei, E);
    csr_scan<<<1, 1024>>>(N);
    csr_fill<<<(E + 255) / 256, 256>>>(ei, edge_attr, E);

    for (int l = 0; l < LL; l++) {
        gat_gemm<<<(N + 63) / 64, 256>>>(gat_lin_w + (size_t)l * 128 * 128,
                                         att_src + l * 128, att_dst + l * 128, N);
        gat_aggr<<<(N + 7) / 8, 256>>>(gat_bias + l * 128, bn_beta + l * 128,
                                       bn_mean + l * 128, N, l);
    }

    zero_readout<<<1024, 256>>>(B);
    readout<<<(N + 7) / 8, 256>>>(batch, N);
    head<<<B, 128>>>(gfeat, gc_w, gc_b, gf1_w, gf1_b, gf2_w, gf2_b,
                     p1_w, p1_b, p2_w, p2_b, p3_w, p3_b, (float*)d_out);
}

// round 5
// speedup vs baseline: 1.1901x; 1.1570x over previous
#include <cuda_runtime.h>
#include <cstdint>

#define NN 100000
#define EE 400000
#define BBATCH 2048
#define HID 128
#define LL 4
#define NEG_SLOPE 0.2f

// ------------------------- device scratch (static, no allocs) ----------------
__device__ __align__(128) float g_h[NN * HID];      // node features (updated per layer)
__device__ __align__(128) float g_xh[NN * HID];     // h @ gat_lin_w[l]
__device__ __align__(128) float g_as[NN * 4];
__device__ __align__(128) float g_ad[NN * 4];
__device__ __align__(128) float g_M[LL * 4 * 4];    // [l][f(3=bias)][h]
__device__ __align__(128) float g_bnscale[LL * HID];
__device__ __align__(128) float g_cnt[BBATCH];
__device__ __align__(128) float g_gsum[BBATCH * HID];
__device__ __align__(128) unsigned g_gmax[BBATCH * HID];
// packed tf32-split weights: [l][q=k/8][t4][n] -> {hi(k=8q+t4), hi(k=8q+t4+4), lo, lo}
__device__ __align__(128) float4 g_wpack[LL * 16 * 4 * 128];
// CSR by destination
__device__ __align__(128) int    g_degi[NN];
__device__ __align__(128) int    g_rowptr[NN + 1];
__device__ __align__(128) int    g_cursor[NN];
__device__ __align__(128) float4 g_csr[EE];         // {src(bits), e0, e1, e2}

// ------------------------- helpers ----------------
__device__ __forceinline__ unsigned enc_f(float f) {
    unsigned u = __float_as_uint(f);
    return (u & 0x80000000u) ? ~u : (u | 0x80000000u);
}
__device__ __forceinline__ float dec_f(unsigned e) {
    return (e & 0x80000000u) ? __uint_as_float(e & 0x7fffffffu) : __uint_as_float(~e);
}
__device__ __forceinline__ unsigned f2tf(float x) {
    unsigned u;
    asm("cvt.rna.tf32.f32 %0, %1;" : "=r"(u) : "f"(x));
    return u;
}
#define MMA_TF32(d, a0, a1, a2, a3, b0, b1)                                       \
    asm volatile("mma.sync.aligned.m16n8k8.row.col.f32.tf32.tf32.f32 "            \
                 "{%0,%1,%2,%3}, {%4,%5,%6,%7}, {%8,%9}, {%0,%1,%2,%3};"          \
                 : "+f"((d)[0]), "+f"((d)[1]), "+f"((d)[2]), "+f"((d)[3])         \
                 : "r"(a0), "r"(a1), "r"(a2), "r"(a3), "r"(b0), "r"(b1))

// ------------------------- setup: w_e_att collapse + bn scale ----------------
__global__ void setup_kernel(const float* __restrict__ edge_w, const float* __restrict__ edge_b,
                             const float* __restrict__ gat_edge_w, const float* __restrict__ att_edge,
                             const float* __restrict__ bn_gamma, const float* __restrict__ bn_var) {
    __shared__ float S[LL * 128 * 4]; // [l][k][h]
    int t = threadIdx.x;
    for (int i = t; i < LL * 128 * 4; i += 256) {
        int l = i >> 9, k = (i >> 2) & 127, h = i & 3;
        const float* wrow = gat_edge_w + (l * 128 + k) * 128 + h * 32;
        const float* arow = att_edge + l * 128 + h * 32;
        float s = 0.f;
        #pragma unroll
        for (int c = 0; c < 32; c++) s += wrow[c] * arow[c];
        S[l * 512 + k * 4 + h] = s;
    }
    __syncthreads();
    if (t < 64) {
        int l = t >> 4, f = (t >> 2) & 3, h = t & 3;
        float m = 0.f;
        if (f < 3) { for (int k = 0; k < 128; k++) m += edge_w[f * 128 + k] * S[l * 512 + k * 4 + h]; }
        else       { for (int k = 0; k < 128; k++) m += edge_b[k] * S[l * 512 + k * 4 + h]; }
        g_M[t] = m;
    }
    for (int i = t; i < LL * HID; i += 256)
        g_bnscale[i] = bn_gamma[i] * rsqrtf(bn_var[i] + 1e-5f);
}

// ------------------------- weight split/pack for tf32 mma -------------------
__global__ void wpack_kernel(const float* __restrict__ gat_lin_w) {
    int i = blockIdx.x * blockDim.x + threadIdx.x;
    if (i >= LL * 16 * 4 * 128) return;
    int l = i >> 13, r = i & 8191;
    int q = r >> 9, t4 = (r >> 7) & 3, n = r & 127;
    const float* W = gat_lin_w + (size_t)l * 16384;
    float w1 = W[(8 * q + t4) * 128 + n];
    float w2 = W[(8 * q + t4 + 4) * 128 + n];
    unsigned h1 = f2tf(w1), h2 = f2tf(w2);
    float h1f = __uint_as_float(h1), h2f = __uint_as_float(h2);
    unsigned l1 = f2tf(w1 - h1f), l2 = f2tf(w2 - h2f);
    g_wpack[i] = make_float4(h1f, h2f, __uint_as_float(l1), __uint_as_float(l2));
}

// ------------------------- node encoder ----------------
__global__ void node_enc(const float* __restrict__ x, const float* __restrict__ w,
                         const float* __restrict__ b, int n) {
    int i = blockIdx.x * blockDim.x + threadIdx.x;
    if (i >= n * HID) return;
    int node = i >> 7, j = i & 127;
    const float* xr = x + node * 7;
    float s = b[j];
    #pragma unroll
    for (int f = 0; f < 7; f++) s += xr[f] * w[f * HID + j];
    g_h[i] = s;
}

// ------------------------- CSR build ----------------
__global__ void zero_degi(int n) {
    int tid = blockIdx.x * blockDim.x + threadIdx.x;
    int stride = gridDim.x * blockDim.x;
    for (int i = tid; i < n; i += stride) g_degi[i] = 0;
}
__global__ void csr_count(const int* __restrict__ ei, int E) {
    int e = blockIdx.x * blockDim.x + threadIdx.x;
    if (e >= E) return;
    atomicAdd(&g_degi[ei[E + e]], 1);
}
__global__ __launch_bounds__(1024) void csr_scan(int n) {
    __shared__ int ssum[1024];
    int t = threadIdx.x;
    int chunk = (n + 1023) >> 10;
    int beg = t * chunk, end = beg + chunk;
    if (end > n) end = n;
    int s = 0;
    for (int i = beg; i < end; i++) s += g_degi[i];
    ssum[t] = s;
    __syncthreads();
    for (int off = 1; off < 1024; off <<= 1) {
        int v = (t >= off) ? ssum[t - off] : 0;
        __syncthreads();
        ssum[t] += v;
        __syncthreads();
    }
    int running = ssum[t] - s;   // exclusive prefix at chunk start
    for (int i = beg; i < end; i++) {
        g_rowptr[i] = running;
        g_cursor[i] = running;
        running += g_degi[i];
    }
    if (t == 1023) g_rowptr[n] = ssum[1023];
}
__global__ void csr_fill(const int* __restrict__ ei, const float* __restrict__ edge_attr, int E) {
    int e = blockIdx.x * blockDim.x + threadIdx.x;
    if (e >= E) return;
    int src = ei[e], dst = ei[E + e];
    int pos = atomicAdd(&g_cursor[dst], 1);
    g_csr[pos] = make_float4(__int_as_float(src),
                             edge_attr[e * 3], edge_attr[e * 3 + 1], edge_attr[e * 3 + 2]);
}

// --------- tensor-core GEMM: xh = h @ W (3-term tf32), + a_s/a_d epilogue ----
// 128 threads = 4 warps; each warp computes 32 rows x 128 cols.
__global__ __launch_bounds__(128) void gat_gemm_tc(int l, const float* __restrict__ atts,
                                                   const float* __restrict__ attd, int n) {
    int t = threadIdx.x;
    int warp = t >> 5, lane = t & 31;
    int g = lane >> 2, t4 = lane & 3;
    int r0 = blockIdx.x * 128 + warp * 32;

    // clamped row pointers (OOB rows duplicate last row; stores are guarded)
    const float* ra[4];
    #pragma unroll
    for (int r = 0; r < 4; r++) {
        int row = r0 + g + r * 8;
        if (row > n - 1) row = n - 1;
        ra[r] = g_h + (size_t)row * 128;
    }

    float acc[2][16][4];
    #pragma unroll
    for (int mt = 0; mt < 2; mt++)
        #pragma unroll
        for (int j = 0; j < 16; j++)
            #pragma unroll
            for (int c = 0; c < 4; c++) acc[mt][j][c] = 0.f;

    const float4* wp = g_wpack + l * 8192;

    #pragma unroll 2
    for (int q = 0; q < 16; q++) {
        int c0 = 8 * q + t4;
        unsigned ahi[4][2], alo[4][2];
        #pragma unroll
        for (int r = 0; r < 4; r++) {
            #pragma unroll
            for (int c = 0; c < 2; c++) {
                float a = ra[r][c0 + c * 4];
                unsigned hi = f2tf(a);
                ahi[r][c] = hi;
                alo[r][c] = f2tf(a - __uint_as_float(hi));
            }
        }
        const float4* wq = wp + q * 512 + t4 * 128 + g;
        #pragma unroll
        for (int j = 0; j < 16; j++) {
            float4 w = wq[8 * j];
            unsigned bh0 = __float_as_uint(w.x), bh1 = __float_as_uint(w.y);
            unsigned bl0 = __float_as_uint(w.z), bl1 = __float_as_uint(w.w);
            #pragma unroll
            for (int mt = 0; mt < 2; mt++) {
                float* d = acc[mt][j];
                MMA_TF32(d, ahi[2 * mt][0], ahi[2 * mt + 1][0], ahi[2 * mt][1], ahi[2 * mt + 1][1], bh0, bh1);
                MMA_TF32(d, alo[2 * mt][0], alo[2 * mt + 1][0], alo[2 * mt][1], alo[2 * mt + 1][1], bh0, bh1);
                MMA_TF32(d, ahi[2 * mt][0], ahi[2 * mt + 1][0], ahi[2 * mt][1], ahi[2 * mt + 1][1], bl0, bl1);
            }
        }
    }

    // epilogue: store xh + per-head attention dots (a_s, a_d)
    #pragma unroll
    for (int mt = 0; mt < 2; mt++) {
        int rA = r0 + mt * 16 + g;
        int rB = rA + 8;
        bool okA = rA < n, okB = rB < n;
        float psA[4] = {0, 0, 0, 0}, pdA[4] = {0, 0, 0, 0};
        float psB[4] = {0, 0, 0, 0}, pdB[4] = {0, 0, 0, 0};
        #pragma unroll
        for (int j = 0; j < 16; j++) {
            float2 s2 = *(const float2*)(atts + 8 * j + 2 * t4);
            float2 d2 = *(const float2*)(attd + 8 * j + 2 * t4);
            int hh = j >> 2;
            float* a = acc[mt][j];
            psA[hh] += a[0] * s2.x + a[1] * s2.y;
            pdA[hh] += a[0] * d2.x + a[1] * d2.y;
            psB[hh] += a[2] * s2.x + a[3] * s2.y;
            pdB[hh] += a[2] * d2.x + a[3] * d2.y;
            if (okA) *(float2*)(g_xh + (size_t)rA * 128 + 8 * j + 2 * t4) = make_float2(a[0], a[1]);
            if (okB) *(float2*)(g_xh + (size_t)rB * 128 + 8 * j + 2 * t4) = make_float2(a[2], a[3]);
        }
        #pragma unroll
        for (int hh = 0; hh < 4; hh++) {
            psA[hh] += __shfl_xor_sync(0xffffffffu, psA[hh], 1);
            psA[hh] += __shfl_xor_sync(0xffffffffu, psA[hh], 2);
            pdA[hh] += __shfl_xor_sync(0xffffffffu, pdA[hh], 1);
            pdA[hh] += __shfl_xor_sync(0xffffffffu, pdA[hh], 2);
            psB[hh] += __shfl_xor_sync(0xffffffffu, psB[hh], 1);
            psB[hh] += __shfl_xor_sync(0xffffffffu, psB[hh], 2);
            pdB[hh] += __shfl_xor_sync(0xffffffffu, pdB[hh], 1);
            pdB[hh] += __shfl_xor_sync(0xffffffffu, pdB[hh], 2);
        }
        if (t4 == 0) {
            if (okA) {
                #pragma unroll
                for (int hh = 0; hh < 4; hh++) {
                    g_as[rA * 4 + hh] = psA[hh];
                    g_ad[rA * 4 + hh] = pdA[hh];
                }
            }
            if (okB) {
                #pragma unroll
                for (int hh = 0; hh < 4; hh++) {
                    g_as[rB * 4 + hh] = psB[hh];
                    g_ad[rB * 4 + hh] = pdB[hh];
                }
            }
        }
    }
}

// --------- fused per-dst aggregation: softmax + bias + BN + relu + residual --
__global__ __launch_bounds__(256) void gat_aggr(const float* __restrict__ gat_bias,
                                                const float* __restrict__ bn_beta,
                                                const float* __restrict__ bn_mean,
                                                int n, int l) {
    int w = (blockIdx.x * blockDim.x + threadIdx.x) >> 5;
    if (w >= n) return;
    int lane = threadIdx.x & 31;
    int hd = lane >> 3;
    bool alead = (lane & 7) == 0;

    float m0 = 0.f, m1 = 0.f, m2 = 0.f, m3 = 0.f, ad = 0.f;
    if (alead) {
        m0 = g_M[l * 16 + hd];      m1 = g_M[l * 16 + 4 + hd];
        m2 = g_M[l * 16 + 8 + hd];  m3 = g_M[l * 16 + 12 + hd];
        ad = g_ad[w * 4 + hd];
    }
    int s = g_rowptr[w], e = g_rowptr[w + 1];

    float4 acc = make_float4(0.f, 0.f, 0.f, 0.f);
    float denom = 0.f;
    float s0 = 0.f, s1 = 0.f, s2 = 0.f;

    for (int i = s; i < e; i++) {
        float4 ent = g_csr[i];
        int src = __float_as_int(ent.x);
        float ex = 0.f;
        if (alead) {
            float ae = ent.y * m0 + ent.z * m1 + ent.w * m2 + m3;
            float alpha = g_as[src * 4 + hd] + ad + ae;
            alpha = alpha > 0.f ? alpha : NEG_SLOPE * alpha;
            ex = __expf(alpha);
            denom += ex;
        }
        ex = __shfl_sync(0xffffffffu, ex, lane & 24);
        float4 xv = *(const float4*)(g_xh + (size_t)src * 128 + lane * 4);
        acc.x += ex * xv.x; acc.y += ex * xv.y; acc.z += ex * xv.z; acc.w += ex * xv.w;
        s0 += ent.y; s1 += ent.z; s2 += ent.w;
    }

    {   // self loop with mean incoming edge feature (0 if isolated)
        float ex = 0.f;
        if (alead) {
            float invd = 1.f / fmaxf((float)(e - s), 1.f);
            float ae = (s0 * m0 + s1 * m1 + s2 * m2) * invd + m3;
            float alpha = g_as[w * 4 + hd] + ad + ae;
            alpha = alpha > 0.f ? alpha : NEG_SLOPE * alpha;
            ex = __expf(alpha);
            denom += ex;
        }
        ex = __shfl_sync(0xffffffffu, ex, lane & 24);
        float4 xv = *(const float4*)(g_xh + (size_t)w * 128 + lane * 4);
        acc.x += ex * xv.x; acc.y += ex * xv.y; acc.z += ex * xv.z; acc.w += ex * xv.w;
    }

    float inv = 0.f;
    if (alead) inv = 1.f / denom;
    inv = __shfl_sync(0xffffffffu, inv, lane & 24);

    int j = lane * 4;
    float4 hres = *(const float4*)(g_h + (size_t)w * 128 + j);
    const float* bs = g_bnscale + l * 128 + j;
    const float* gb = gat_bias + j;
    const float* bm = bn_mean + j;
    const float* bb = bn_beta + j;
    float4 r;
    r.x = fmaxf((acc.x * inv + gb[0] - bm[0]) * bs[0] + bb[0], 0.f) + hres.x;
    r.y = fmaxf((acc.y * inv + gb[1] - bm[1]) * bs[1] + bb[1], 0.f) + hres.y;
    r.z = fmaxf((acc.z * inv + gb[2] - bm[2]) * bs[2] + bb[2], 0.f) + hres.z;
    r.w = fmaxf((acc.w * inv + gb[3] - bm[3]) * bs[3] + bb[3], 0.f) + hres.w;
    *(float4*)(g_h + (size_t)w * 128 + j) = r;
}

// ------------------------- readout: per-batch cnt/sum/max ----------------
__global__ void zero_readout(int b) {
    int tid = blockIdx.x * blockDim.x + threadIdx.x;
    int stride = gridDim.x * blockDim.x;
    for (int i = tid; i < b; i += stride) g_cnt[i] = 0.f;
    for (int i = tid; i < b * HID; i += stride) { g_gsum[i] = 0.f; g_gmax[i] = 0x007fffffu; }
}
__global__ __launch_bounds__(256) void readout(const int* __restrict__ batch, int n) {
    int widx = (blockIdx.x * blockDim.x + threadIdx.x) >> 5;
    int lane = threadIdx.x & 31;
    if (widx >= n) return;
    int b = batch[widx];
    if (lane == 0) atomicAdd(&g_cnt[b], 1.0f);
    float4 v = *(const float4*)(g_h + (size_t)widx * 128 + lane * 4);
    float* sp = g_gsum + b * 128 + lane * 4;
    asm volatile("red.global.add.v4.f32 [%0], {%1,%2,%3,%4};"
                 :: "l"(sp), "f"(v.x), "f"(v.y), "f"(v.z), "f"(v.w) : "memory");
    unsigned* mp = g_gmax + b * 128 + lane * 4;
    atomicMax(mp + 0, enc_f(v.x));
    atomicMax(mp + 1, enc_f(v.y));
    atomicMax(mp + 2, enc_f(v.z));
    atomicMax(mp + 3, enc_f(v.w));
}

// ------------------------- fused head MLP (one block per graph) -------------
__global__ __launch_bounds__(128) void head(const float* __restrict__ gfeat,
        const float* __restrict__ gc_w, const float* __restrict__ gc_b,
        const float* __restrict__ gf1_w, const float* __restrict__ gf1_b,
        const float* __restrict__ gf2_w, const float* __restrict__ gf2_b,
        const float* __restrict__ p1_w, const float* __restrict__ p1_b,
        const float* __restrict__ p2_w, const float* __restrict__ p2_b,
        const float* __restrict__ p3_w, const float* __restrict__ p3_b,
        float* __restrict__ out) {
    int b = blockIdx.x, t = threadIdx.x;
    __shared__ float sG[384], sC[192], sT[64], sH1[128], sH2[64];
    float cnt = g_cnt[b];
    float inv = 1.0f / fmaxf(cnt, 1.0f);
    float gs = g_gsum[b * 128 + t];
    sG[t] = gs * inv;
    float mx = dec_f(g_gmax[b * 128 + t]);
    sG[128 + t] = (cnt > 0.f) ? mx : 0.f;
    sG[256 + t] = gs;
    if (t < 64) {
        float s = gf1_b[t];
        #pragma unroll
        for (int k = 0; k < 10; k++) s += gfeat[b * 10 + k] * gf1_w[k * 64 + t];
        sT[t] = fmaxf(s, 0.f);
    }
    __syncthreads();
    {
        float s = gc_b[t];
        #pragma unroll 8
        for (int k = 0; k < 384; k++) s += sG[k] * gc_w[k * 128 + t];
        sC[t] = fmaxf(s, 0.f);
    }
    if (t < 64) {
        float s = gf2_b[t];
        #pragma unroll 8
        for (int k = 0; k < 64; k++) s += sT[k] * gf2_w[k * 64 + t];
        sC[128 + t] = s;
    }
    __syncthreads();
    {
        float s = p1_b[t];
        #pragma unroll 8
        for (int k = 0; k < 192; k++) s += sC[k] * p1_w[k * 128 + t];
        sH1[t] = fmaxf(s, 0.f);
    }
    __syncthreads();
    if (t < 64) {
        float s = p2_b[t];
        #pragma unroll 8
        for (int k = 0; k < 128; k++) s += sH1[k] * p2_w[k * 64 + t];
        sH2[t] = fmaxf(s, 0.f);
    }
    __syncthreads();
    if (t < 5) {
        float s = p3_b[t];
        #pragma unroll
        for (int k = 0; k < 64; k++) s += sH2[k] * p3_w[k * 5 + t];
        out[b * 5 + t] = s;
    }
}

// ------------------------- launch ----------------
extern "C" void kernel_launch(void* const* d_in, const int* in_sizes, int n_in,
                              void* d_out, int out_size) {
    const float* x          = (const float*)d_in[0];
    const int*   ei         = (const int*)d_in[1];
    const float* edge_attr  = (const float*)d_in[2];
    const int*   batch      = (const int*)d_in[3];
    const float* gfeat      = (const float*)d_in[4];
    const float* node_w     = (const float*)d_in[5];
    const float* node_b     = (const float*)d_in[6];
    const float* edge_w     = (const float*)d_in[7];
    const float* edge_b     = (const float*)d_in[8];
    const float* gat_lin_w  = (const float*)d_in[9];
    const float* gat_edge_w = (const float*)d_in[10];
    const float* att_src    = (const float*)d_in[11];
    const float* att_dst    = (const float*)d_in[12];
    const float* att_edge   = (const float*)d_in[13];
    const float* gat_bias   = (const float*)d_in[14];
    const float* bn_gamma   = (const float*)d_in[15];
    const float* bn_beta    = (const float*)d_in[16];
    const float* bn_mean    = (const float*)d_in[17];
    const float* bn_var     = (const float*)d_in[18];
    const float* gc_w       = (const float*)d_in[19];
    const float* gc_b       = (const float*)d_in[20];
    const float* gf1_w      = (const float*)d_in[21];
    const float* gf1_b      = (const float*)d_in[22];
    const float* gf2_w      = (const float*)d_in[23];
    const float* gf2_b      = (const float*)d_in[24];
    const float* p1_w       = (const float*)d_in[25];
    const float* p1_b       = (const float*)d_in[26];
    const float* p2_w       = (const float*)d_in[27];
    const float* p2_b       = (const float*)d_in[28];
    const float* p3_w       = (const float*)d_in[29];
    const float* p3_b       = (const float*)d_in[30];

    int N = in_sizes[0] / 7;
    int E = in_sizes[1] / 2;
    int B = in_sizes[4] / 10;
    if (N > NN) N = NN;
    if (E > EE) E = EE;
    if (B > BBATCH) B = BBATCH;

    setup_kernel<<<1, 256>>>(edge_w, edge_b, gat_edge_w, att_edge, bn_gamma, bn_var);
    wpack_kernel<<<(LL * 16 * 4 * 128 + 255) / 256, 256>>>(gat_lin_w);
    node_enc<<<(N * HID + 255) / 256, 256>>>(x, node_w, node_b, N);

    // CSR build (once)
    zero_degi<<<256, 256>>>(N);
    csr_count<<<(E + 255) / 256, 256>>>(ei, E);
    csr_scan<<<1, 1024>>>(N);
    csr_fill<<<(E + 255) / 256, 256>>>(ei, edge_attr, E);

    for (int l = 0; l < LL; l++) {
        gat_gemm_tc<<<(N + 127) / 128, 128>>>(l, att_src + l * 128, att_dst + l * 128, N);
        gat_aggr<<<(N + 7) / 8, 256>>>(gat_bias + l * 128, bn_beta + l * 128,
                                       bn_mean + l * 128, N, l);
    }

    zero_readout<<<1024, 256>>>(B);
    readout<<<(N + 7) / 8, 256>>>(batch, N);
    head<<<B, 128>>>(gfeat, gc_w, gc_b, gf1_w, gf1_b, gf2_w, gf2_b,
                     p1_w, p1_b, p2_w, p2_b, p3_w, p3_b, (float*)d_out);
}

// round 7
// speedup vs baseline: 1.2035x; 1.0113x over previous
#include <cuda_runtime.h>
#include <cuda_fp16.h>
#include <cstdint>

#define NN 100000
#define EE 400000
#define BBATCH 2048
#define HID 128
#define LL 4
#define NEG_SLOPE 0.2f

// ------------------------- device scratch (static, no allocs) ----------------
__device__ __align__(128) float  g_h[NN * HID];     // node features (updated per layer)
__device__ __align__(128) __half g_xh[NN * HID];    // h @ gat_lin_w[l]  (fp16)
__device__ __align__(128) float  g_as[NN * 4];
__device__ __align__(128) float  g_ad[NN * 4];
__device__ __align__(128) float  g_M[LL * 4 * 4];   // [l][f(3=bias)][h]
__device__ __align__(128) float  g_bnscale[LL * HID];
__device__ __align__(128) float  g_cnt[BBATCH];
__device__ __align__(128) float  g_gsum[BBATCH * HID];
__device__ __align__(128) unsigned g_gmax[BBATCH * HID];
// packed tf32-split weights: [l][q=k/8][t4][n] -> {hi(k=8q+t4), hi(k=8q+t4+4), lo, lo}
__device__ __align__(128) float4 g_wpack[LL * 16 * 4 * 128];
// CSR by destination
__device__ __align__(128) int    g_degi[NN];
__device__ __align__(128) int    g_rowptr[NN + 1];
__device__ __align__(128) int    g_cursor[NN];
__device__ __align__(128) float4 g_csr[EE];         // {src(bits), e0, e1, e2}

// ------------------------- helpers ----------------
__device__ __forceinline__ unsigned enc_f(float f) {
    unsigned u = __float_as_uint(f);
    return (u & 0x80000000u) ? ~u : (u | 0x80000000u);
}
__device__ __forceinline__ float dec_f(unsigned e) {
    return (e & 0x80000000u) ? __uint_as_float(e & 0x7fffffffu) : __uint_as_float(~e);
}
__device__ __forceinline__ unsigned f2tf(float x) {
    unsigned u;
    asm("cvt.rna.tf32.f32 %0, %1;" : "=r"(u) : "f"(x));
    return u;
}
#define MMA_TF32(d, a0, a1, a2, a3, b0, b1)                                       \
    asm volatile("mma.sync.aligned.m16n8k8.row.col.f32.tf32.tf32.f32 "            \
                 "{%0,%1,%2,%3}, {%4,%5,%6,%7}, {%8,%9}, {%0,%1,%2,%3};"          \
                 : "+f"((d)[0]), "+f"((d)[1]), "+f"((d)[2]), "+f"((d)[3])         \
                 : "r"(a0), "r"(a1), "r"(a2), "r"(a3), "r"(b0), "r"(b1))

// ------------------------- setup: w_e_att collapse + bn scale ----------------
__global__ void setup_kernel(const float* __restrict__ edge_w, const float* __restrict__ edge_b,
                             const float* __restrict__ gat_edge_w, const float* __restrict__ att_edge,
                             const float* __restrict__ bn_gamma, const float* __restrict__ bn_var) {
    __shared__ float S[LL * 128 * 4]; // [l][k][h]
    int t = threadIdx.x;
    for (int i = t; i < LL * 128 * 4; i += 256) {
        int l = i >> 9, k = (i >> 2) & 127, h = i & 3;
        const float* wrow = gat_edge_w + (l * 128 + k) * 128 + h * 32;
        const float* arow = att_edge + l * 128 + h * 32;
        float s = 0.f;
        #pragma unroll
        for (int c = 0; c < 32; c++) s += wrow[c] * arow[c];
        S[l * 512 + k * 4 + h] = s;
    }
    __syncthreads();
    if (t < 64) {
        int l = t >> 4, f = (t >> 2) & 3, h = t & 3;
        float m = 0.f;
        if (f < 3) { for (int k = 0; k < 128; k++) m += edge_w[f * 128 + k] * S[l * 512 + k * 4 + h]; }
        else       { for (int k = 0; k < 128; k++) m += edge_b[k] * S[l * 512 + k * 4 + h]; }
        g_M[t] = m;
    }
    for (int i = t; i < LL * HID; i += 256)
        g_bnscale[i] = bn_gamma[i] * rsqrtf(bn_var[i] + 1e-5f);
}

// ------------------------- weight split/pack for tf32 mma -------------------
__global__ void wpack_kernel(const float* __restrict__ gat_lin_w) {
    int i = blockIdx.x * blockDim.x + threadIdx.x;
    if (i >= LL * 16 * 4 * 128) return;
    int l = i >> 13, r = i & 8191;
    int q = r >> 9, t4 = (r >> 7) & 3, n = r & 127;
    const float* W = gat_lin_w + (size_t)l * 16384;
    float w1 = W[(8 * q + t4) * 128 + n];
    float w2 = W[(8 * q + t4 + 4) * 128 + n];
    unsigned h1 = f2tf(w1), h2 = f2tf(w2);
    float h1f = __uint_as_float(h1), h2f = __uint_as_float(h2);
    unsigned l1 = f2tf(w1 - h1f), l2 = f2tf(w2 - h2f);
    g_wpack[i] = make_float4(h1f, h2f, __uint_as_float(l1), __uint_as_float(l2));
}

// ------------------------- node encoder ----------------
__global__ void node_enc(const float* __restrict__ x, const float* __restrict__ w,
                         const float* __restrict__ b, int n) {
    int i = blockIdx.x * blockDim.x + threadIdx.x;
    if (i >= n * HID) return;
    int node = i >> 7, j = i & 127;
    const float* xr = x + node * 7;
    float s = b[j];
    #pragma unroll
    for (int f = 0; f < 7; f++) s += xr[f] * w[f * HID + j];
    g_h[i] = s;
}

// ------------------------- zero (degi + readout buffers) ----------------
__global__ void zero_misc(int n, int b) {
    int tid = blockIdx.x * blockDim.x + threadIdx.x;
    int stride = gridDim.x * blockDim.x;
    for (int i = tid; i < n; i += stride) g_degi[i] = 0;
    for (int i = tid; i < b; i += stride) g_cnt[i] = 0.f;
    for (int i = tid; i < b * HID; i += stride) { g_gsum[i] = 0.f; g_gmax[i] = 0x007fffffu; }
}

// ------------------------- CSR build ----------------
__global__ void csr_count(const int* __restrict__ ei, int E) {
    int e = blockIdx.x * blockDim.x + threadIdx.x;
    if (e >= E) return;
    atomicAdd(&g_degi[ei[E + e]], 1);
}
__global__ __launch_bounds__(1024) void csr_scan(int n) {
    __shared__ int ssum[1024];
    int t = threadIdx.x;
    int chunk = (n + 1023) >> 10;
    int beg = t * chunk, end = beg + chunk;
    if (end > n) end = n;
    int s = 0;
    for (int i = beg; i < end; i++) s += g_degi[i];
    ssum[t] = s;
    __syncthreads();
    for (int off = 1; off < 1024; off <<= 1) {
        int v = (t >= off) ? ssum[t - off] : 0;
        __syncthreads();
        ssum[t] += v;
        __syncthreads();
    }
    int running = ssum[t] - s;   // exclusive prefix at chunk start
    for (int i = beg; i < end; i++) {
        g_rowptr[i] = running;
        g_cursor[i] = running;
        running += g_degi[i];
    }
    if (t == 1023) g_rowptr[n] = ssum[1023];
}
__global__ void csr_fill(const int* __restrict__ ei, const float* __restrict__ edge_attr, int E) {
    int e = blockIdx.x * blockDim.x + threadIdx.x;
    if (e >= E) return;
    int src = ei[e], dst = ei[E + e];
    int pos = atomicAdd(&g_cursor[dst], 1);
    g_csr[pos] = make_float4(__int_as_float(src),
                             edge_attr[e * 3], edge_attr[e * 3 + 1], edge_attr[e * 3 + 2]);
}

// --------- tensor-core GEMM: xh = h @ W (3-term tf32), + a_s/a_d epilogue ----
// 128 threads = 4 warps; each warp computes 32 rows x 128 cols.
__global__ __launch_bounds__(128) void gat_gemm_tc(int l, const float* __restrict__ atts,
                                                   const float* __restrict__ attd, int n) {
    int t = threadIdx.x;
    int warp = t >> 5, lane = t & 31;
    int g = lane >> 2, t4 = lane & 3;
    int r0 = blockIdx.x * 128 + warp * 32;

    // clamped row pointers (OOB rows duplicate last row; stores are guarded)
    const float* ra[4];
    #pragma unroll
    for (int r = 0; r < 4; r++) {
        int row = r0 + g + r * 8;
        if (row > n - 1) row = n - 1;
        ra[r] = g_h + (size_t)row * 128;
    }

    float acc[2][16][4];
    #pragma unroll
    for (int mt = 0; mt < 2; mt++)
        #pragma unroll
        for (int j = 0; j < 16; j++)
            #pragma unroll
            for (int c = 0; c < 4; c++) acc[mt][j][c] = 0.f;

    const float4* wp = g_wpack + l * 8192;

    #pragma unroll 2
    for (int q = 0; q < 16; q++) {
        int c0 = 8 * q + t4;
        unsigned ahi[4][2], alo[4][2];
        #pragma unroll
        for (int r = 0; r < 4; r++) {
            #pragma unroll
            for (int c = 0; c < 2; c++) {
                float a = ra[r][c0 + c * 4];
                unsigned hi = f2tf(a);
                ahi[r][c] = hi;
                alo[r][c] = f2tf(a - __uint_as_float(hi));
            }
        }
        const float4* wq = wp + q * 512 + t4 * 128 + g;
        #pragma unroll
        for (int j = 0; j < 16; j++) {
            float4 w = wq[8 * j];
            unsigned bh0 = __float_as_uint(w.x), bh1 = __float_as_uint(w.y);
            unsigned bl0 = __float_as_uint(w.z), bl1 = __float_as_uint(w.w);
            #pragma unroll
            for (int mt = 0; mt < 2; mt++) {
                float* d = acc[mt][j];
                MMA_TF32(d, ahi[2 * mt][0], ahi[2 * mt + 1][0], ahi[2 * mt][1], ahi[2 * mt + 1][1], bh0, bh1);
                MMA_TF32(d, alo[2 * mt][0], alo[2 * mt + 1][0], alo[2 * mt][1], alo[2 * mt + 1][1], bh0, bh1);
                MMA_TF32(d, ahi[2 * mt][0], ahi[2 * mt + 1][0], ahi[2 * mt][1], ahi[2 * mt + 1][1], bl0, bl1);
            }
        }
    }

    // epilogue: store xh (fp16) + per-head attention dots (a_s, a_d, fp32)
    #pragma unroll
    for (int mt = 0; mt < 2; mt++) {
        int rA = r0 + mt * 16 + g;
        int rB = rA + 8;
        bool okA = rA < n, okB = rB < n;
        float psA[4] = {0, 0, 0, 0}, pdA[4] = {0, 0, 0, 0};
        float psB[4] = {0, 0, 0, 0}, pdB[4] = {0, 0, 0, 0};
        #pragma unroll
        for (int j = 0; j < 16; j++) {
            float2 s2 = *(const float2*)(atts + 8 * j + 2 * t4);
            float2 d2 = *(const float2*)(attd + 8 * j + 2 * t4);
            int hh = j >> 2;
            float* a = acc[mt][j];
            psA[hh] += a[0] * s2.x + a[1] * s2.y;
            pdA[hh] += a[0] * d2.x + a[1] * d2.y;
            psB[hh] += a[2] * s2.x + a[3] * s2.y;
            pdB[hh] += a[2] * d2.x + a[3] * d2.y;
            if (okA) *(__half2*)(g_xh + (size_t)rA * 128 + 8 * j + 2 * t4) = __floats2half2_rn(a[0], a[1]);
            if (okB) *(__half2*)(g_xh + (size_t)rB * 128 + 8 * j + 2 * t4) = __floats2half2_rn(a[2], a[3]);
        }
        #pragma unroll
        for (int hh = 0; hh < 4; hh++) {
            psA[hh] += __shfl_xor_sync(0xffffffffu, psA[hh], 1);
            psA[hh] += __shfl_xor_sync(0xffffffffu, psA[hh], 2);
            pdA[hh] += __shfl_xor_sync(0xffffffffu, pdA[hh], 1);
            pdA[hh] += __shfl_xor_sync(0xffffffffu, pdA[hh], 2);
            psB[hh] += __shfl_xor_sync(0xffffffffu, psB[hh], 1);
            psB[hh] += __shfl_xor_sync(0xffffffffu, psB[hh], 2);
            pdB[hh] += __shfl_xor_sync(0xffffffffu, pdB[hh], 1);
            pdB[hh] += __shfl_xor_sync(0xffffffffu, pdB[hh], 2);
        }
        if (t4 == 0) {
            if (okA) {
                #pragma unroll
                for (int hh = 0; hh < 4; hh++) {
                    g_as[rA * 4 + hh] = psA[hh];
                    g_ad[rA * 4 + hh] = pdA[hh];
                }
            }
            if (okB) {
                #pragma unroll
                for (int hh = 0; hh < 4; hh++) {
                    g_as[rB * 4 + hh] = psB[hh];
                    g_ad[rB * 4 + hh] = pdB[hh];
                }
            }
        }
    }
}

// --------- fused per-dst aggregation: softmax + bias + BN + relu + residual --
__global__ __launch_bounds__(256) void gat_aggr(const float* __restrict__ gat_bias,
                                                const float* __restrict__ bn_beta,
                                                const float* __restrict__ bn_mean,
                                                int n, int l) {
    int w = (blockIdx.x * blockDim.x + threadIdx.x) >> 5;
    if (w >= n) return;
    int lane = threadIdx.x & 31;
    int hd = lane >> 3;
    bool alead = (lane & 7) == 0;

    float m0 = 0.f, m1 = 0.f, m2 = 0.f, m3 = 0.f, ad = 0.f;
    if (alead) {
        m0 = g_M[l * 16 + hd];      m1 = g_M[l * 16 + 4 + hd];
        m2 = g_M[l * 16 + 8 + hd];  m3 = g_M[l * 16 + 12 + hd];
        ad = g_ad[w * 4 + hd];
    }
    int s = g_rowptr[w], e = g_rowptr[w + 1];

    float4 acc = make_float4(0.f, 0.f, 0.f, 0.f);
    float denom = 0.f;
    float s0 = 0.f, s1 = 0.f, s2 = 0.f;

    float4 ent = (s < e) ? g_csr[s] : make_float4(0.f, 0.f, 0.f, 0.f);
    for (int i = s; i < e; i++) {
        float4 nxt = (i + 1 < e) ? g_csr[i + 1] : make_float4(0.f, 0.f, 0.f, 0.f);
        int src = __float_as_int(ent.x);
        float ex = 0.f;
        if (alead) {
            float ae = ent.y * m0 + ent.z * m1 + ent.w * m2 + m3;
            float alpha = g_as[src * 4 + hd] + ad + ae;
            alpha = alpha > 0.f ? alpha : NEG_SLOPE * alpha;
            ex = __expf(alpha);
            denom += ex;
        }
        ex = __shfl_sync(0xffffffffu, ex, lane & 24);
        uint2 xr = *(const uint2*)(g_xh + (size_t)src * 128 + lane * 4);
        float2 f0 = __half22float2(*(__half2*)&xr.x);
        float2 f1 = __half22float2(*(__half2*)&xr.y);
        acc.x += ex * f0.x; acc.y += ex * f0.y; acc.z += ex * f1.x; acc.w += ex * f1.y;
        s0 += ent.y; s1 += ent.z; s2 += ent.w;
        ent = nxt;
    }

    {   // self loop with mean incoming edge feature (0 if isolated)
        float ex = 0.f;
        if (alead) {
            float invd = 1.f / fmaxf((float)(e - s), 1.f);
            float ae = (s0 * m0 + s1 * m1 + s2 * m2) * invd + m3;
            float alpha = g_as[w * 4 + hd] + ad + ae;
            alpha = alpha > 0.f ? alpha : NEG_SLOPE * alpha;
            ex = __expf(alpha);
            denom += ex;
        }
        ex = __shfl_sync(0xffffffffu, ex, lane & 24);
        uint2 xr = *(const uint2*)(g_xh + (size_t)w * 128 + lane * 4);
        float2 f0 = __half22float2(*(__half2*)&xr.x);
        float2 f1 = __half22float2(*(__half2*)&xr.y);
        acc.x += ex * f0.x; acc.y += ex * f0.y; acc.z += ex * f1.x; acc.w += ex * f1.y;
    }

    float inv = 0.f;
    if (alead) inv = 1.f / denom;
    inv = __shfl_sync(0xffffffffu, inv, lane & 24);

    int j = lane * 4;
    float4 hres = *(const float4*)(g_h + (size_t)w * 128 + j);
    const float* bs = g_bnscale + l * 128 + j;
    const float* gb = gat_bias + j;
    const float* bm = bn_mean + j;
    const float* bb = bn_beta + j;
    float4 r;
    r.x = fmaxf((acc.x * inv + gb[0] - bm[0]) * bs[0] + bb[0], 0.f) + hres.x;
    r.y = fmaxf((acc.y * inv + gb[1] - bm[1]) * bs[1] + bb[1], 0.f) + hres.y;
    r.z = fmaxf((acc.z * inv + gb[2] - bm[2]) * bs[2] + bb[2], 0.f) + hres.z;
    r.w = fmaxf((acc.w * inv + gb[3] - bm[3]) * bs[3] + bb[3], 0.f) + hres.w;
    *(float4*)(g_h + (size_t)w * 128 + j) = r;
}

// ------------------------- readout: per-batch cnt/sum/max ----------------
__global__ __launch_bounds__(256) void readout(const int* __restrict__ batch, int n) {
    int widx = (blockIdx.x * blockDim.x + threadIdx.x) >> 5;
    int lane = threadIdx.x & 31;
    if (widx >= n) return;
    int b = batch[widx];
    if (lane == 0) atomicAdd(&g_cnt[b], 1.0f);
    float4 v = *(const float4*)(g_h + (size_t)widx * 128 + lane * 4);
    float* sp = g_gsum + b * 128 + lane * 4;
    asm volatile("red.global.add.v4.f32 [%0], {%1,%2,%3,%4};"
                 :: "l"(sp), "f"(v.x), "f"(v.y), "f"(v.z), "f"(v.w) : "memory");
    unsigned* mp = g_gmax + b * 128 + lane * 4;
    atomicMax(mp + 0, enc_f(v.x));
    atomicMax(mp + 1, enc_f(v.y));
    atomicMax(mp + 2, enc_f(v.z));
    atomicMax(mp + 3, enc_f(v.w));
}

// ------------------------- fused head MLP (one block per graph) -------------
__global__ __launch_bounds__(128) void head(const float* __restrict__ gfeat,
        const float* __restrict__ gc_w, const float* __restrict__ gc_b,
        const float* __restrict__ gf1_w, const float* __restrict__ gf1_b,
        const float* __restrict__ gf2_w, const float* __restrict__ gf2_b,
        const float* __restrict__ p1_w, const float* __restrict__ p1_b,
        const float* __restrict__ p2_w, const float* __restrict__ p2_b,
        const float* __restrict__ p3_w, const float* __restrict__ p3_b,
        float* __restrict__ out) {
    int b = blockIdx.x, t = threadIdx.x;
    __shared__ float sG[384], sC[192], sT[64], sH1[128], sH2[64];
    float cnt = g_cnt[b];
    float inv = 1.0f / fmaxf(cnt, 1.0f);
    float gs = g_gsum[b * 128 + t];
    sG[t] = gs * inv;
    float mx = dec_f(g_gmax[b * 128 + t]);
    sG[128 + t] = (cnt > 0.f) ? mx : 0.f;
    sG[256 + t] = gs;
    if (t < 64) {
        float s = gf1_b[t];
        #pragma unroll
        for (int k = 0; k < 10; k++) s += gfeat[b * 10 + k] * gf1_w[k * 64 + t];
        sT[t] = fmaxf(s, 0.f);
    }
    __syncthreads();
    {
        float s = gc_b[t];
        #pragma unroll 8
        for (int k = 0; k < 384; k++) s += sG[k] * gc_w[k * 128 + t];
        sC[t] = fmaxf(s, 0.f);
    }
    if (t < 64) {
        float s = gf2_b[t];
        #pragma unroll 8
        for (int k = 0; k < 64; k++) s += sT[k] * gf2_w[k * 64 + t];
        sC[128 + t] = s;
    }
    __syncthreads();
    {
        float s = p1_b[t];
        #pragma unroll 8
        for (int k = 0; k < 192; k++) s += sC[k] * p1_w[k * 128 + t];
        sH1[t] = fmaxf(s, 0.f);
    }
    __syncthreads();
    if (t < 64) {
        float s = p2_b[t];
        #pragma unroll 8
        for (int k = 0; k < 128; k++) s += sH1[k] * p2_w[k * 64 + t];
        sH2[t] = fmaxf(s, 0.f);
    }
    __syncthreads();
    if (t < 5) {
        float s = p3_b[t];
        #pragma unroll
        for (int k = 0; k < 64; k++) s += sH2[k] * p3_w[k * 5 + t];
        out[b * 5 + t] = s;
    }
}

// ------------------------- launch ----------------
extern "C" void kernel_launch(void* const* d_in, const int* in_sizes, int n_in,
                              void* d_out, int out_size) {
    const float* x          = (const float*)d_in[0];
    const int*   ei         = (const int*)d_in[1];
    const float* edge_attr  = (const float*)d_in[2];
    const int*   batch      = (const int*)d_in[3];
    const float* gfeat      = (const float*)d_in[4];
    const float* node_w     = (const float*)d_in[5];
    const float* node_b     = (const float*)d_in[6];
    const float* edge_w     = (const float*)d_in[7];
    const float* edge_b     = (const float*)d_in[8];
    const float* gat_lin_w  = (const float*)d_in[9];
    const float* gat_edge_w = (const float*)d_in[10];
    const float* att_src    = (const float*)d_in[11];
    const float* att_dst    = (const float*)d_in[12];
    const float* att_edge   = (const float*)d_in[13];
    const float* gat_bias   = (const float*)d_in[14];
    const float* bn_gamma   = (const float*)d_in[15];
    const float* bn_beta    = (const float*)d_in[16];
    const float* bn_mean    = (const float*)d_in[17];
    const float* bn_var     = (const float*)d_in[18];
    const float* gc_w       = (const float*)d_in[19];
    const float* gc_b       = (const float*)d_in[20];
    const float* gf1_w      = (const float*)d_in[21];
    const float* gf1_b      = (const float*)d_in[22];
    const float* gf2_w      = (const float*)d_in[23];
    const float* gf2_b      = (const float*)d_in[24];
    const float* p1_w       = (const float*)d_in[25];
    const float* p1_b       = (const float*)d_in[26];
    const float* p2_w       = (const float*)d_in[27];
    const float* p2_b       = (const float*)d_in[28];
    const float* p3_w       = (const float*)d_in[29];
    const float* p3_b       = (const float*)d_in[30];

    int N = in_sizes[0] / 7;
    int E = in_sizes[1] / 2;
    int B = in_sizes[4] / 10;
    if (N > NN) N = NN;
    if (E > EE) E = EE;
    if (B > BBATCH) B = BBATCH;

    // launch order: gat_gemm_tc at index 3 so ncu (-s) profiles it next round
    setup_kernel<<<1, 256>>>(edge_w, edge_b, gat_edge_w, att_edge, bn_gamma, bn_var);
    wpack_kernel<<<(LL * 16 * 4 * 128 + 255) / 256, 256>>>(gat_lin_w);
    node_enc<<<(N * HID + 255) / 256, 256>>>(x, node_w, node_b, N);
    gat_gemm_tc<<<(N + 127) / 128, 128>>>(0, att_src, att_dst, N);

    // CSR build (once) — independent of gemm result
    zero_misc<<<1024, 256>>>(N, B);
    csr_count<<<(E + 255) / 256, 256>>>(ei, E);
    csr_scan<<<1, 1024>>>(N);
    csr_fill<<<(E + 255) / 256, 256>>>(ei, edge_attr, E);

    gat_aggr<<<(N + 7) / 8, 256>>>(gat_bias, bn_beta, bn_mean, N, 0);
    for (int l = 1; l < LL; l++) {
        gat_gemm_tc<<<(N + 127) / 128, 128>>>(l, att_src + l * 128, att_dst + l * 128, N);
        gat_aggr<<<(N + 7) / 8, 256>>>(gat_bias + l * 128, bn_beta + l * 128,
                                       bn_mean + l * 128, N, l);
    }

    readout<<<(N + 7) / 8, 256>>>(batch, N);
    head<<<B, 128>>>(gfeat, gc_w, gc_b, gf1_w, gf1_b, gf2_w, gf2_b,
                     p1_w, p1_b, p2_w, p2_b, p3_w, p3_b, (float*)d_out);
}